// round 7
// baseline (speedup 1.0000x reference)
#include <cuda_runtime.h>
#include <math.h>
#include <stdint.h>

// Problem constants
#define B_  4
#define T_  2048
#define C_  1024
#define L_  256
#define H_  16
#define HS_ 64
#define BT_ (B_ * T_)   // 8192

// Scratch (allocation-free rule: __device__ globals)
__device__ float g_q[BT_ * C_];
__device__ float g_lat[BT_ * L_];
__device__ float g_k[BT_ * C_];
__device__ float g_v[BT_ * C_];
__device__ float g_y[BT_ * C_];
__device__ float g_dummy[32];

__device__ __forceinline__ uint32_t f2tf(float f) {
    uint32_t u;
    asm("cvt.rna.tf32.f32 %0, %1;" : "=r"(u) : "f"(f));
    return u;
}

__device__ __forceinline__ void cp_async16(uint32_t dst, const void* src) {
    asm volatile("cp.async.cg.shared.global [%0], [%1], 16;" :: "r"(dst), "l"(src));
}
#define CP_COMMIT() asm volatile("cp.async.commit_group;")
#define CP_WAIT0()  asm volatile("cp.async.wait_group 0;" ::: "memory")

#define MMA_TF32(d, a, b)                                                     \
    asm volatile(                                                             \
        "mma.sync.aligned.m16n8k8.row.col.f32.tf32.tf32.f32 "                 \
        "{%0,%1,%2,%3}, {%4,%5,%6,%7}, {%8,%9}, {%0,%1,%2,%3};"               \
        : "+f"((d)[0]), "+f"((d)[1]), "+f"((d)[2]), "+f"((d)[3])              \
        : "r"((a)[0]), "r"((a)[1]), "r"((a)[2]), "r"((a)[3]),                 \
          "r"((b)[0]), "r"((b)[1]))

// ---------------------------------------------------------------------------
// TF32 tensor-core GEMM (unchanged structure; epilogue scale + tf32 round)
// ---------------------------------------------------------------------------
#define APAD 20
#define BPAD 136

__global__ __launch_bounds__(256, 2)
void gemm_tf32(const float* __restrict__ A, const float* __restrict__ Bg,
               float* __restrict__ Cg, int M, int N, int K,
               float oscale, int round_out) {
    __shared__ uint32_t As[128 * APAD];
    __shared__ uint32_t Bs[16 * BPAD];

    const int tid = threadIdx.x;
    const int m0 = blockIdx.y * 128;
    const int n0 = blockIdx.x * 128;

    const int warp = tid >> 5;
    const int lane = tid & 31;
    const int wm = (warp & 1) * 64;
    const int wn = (warp >> 1) * 32;
    const int g = lane >> 2;
    const int c = lane & 3;

    const int arow = tid >> 1;
    const int ak   = (tid & 1) * 8;
    const int bkr  = tid >> 4;
    const int bcl  = (tid & 15) * 8;

    const float* Aptr = A + (size_t)(m0 + arow) * K + ak;
    const float* Bptr = Bg + (size_t)bkr * N + n0 + bcl;

    float4 pa0 = *(const float4*)(Aptr);
    float4 pa1 = *(const float4*)(Aptr + 4);
    float4 pb0 = *(const float4*)(Bptr);
    float4 pb1 = *(const float4*)(Bptr + 4);

    float acc[4][4][4];
    #pragma unroll
    for (int i = 0; i < 4; i++)
        #pragma unroll
        for (int j = 0; j < 4; j++)
            #pragma unroll
            for (int r = 0; r < 4; r++) acc[i][j][r] = 0.f;

    for (int kt = 0; kt < K; kt += 16) {
        {
            uint32_t* as = &As[arow * APAD + ak];
            as[0] = f2tf(pa0.x); as[1] = f2tf(pa0.y);
            as[2] = f2tf(pa0.z); as[3] = f2tf(pa0.w);
            as[4] = f2tf(pa1.x); as[5] = f2tf(pa1.y);
            as[6] = f2tf(pa1.z); as[7] = f2tf(pa1.w);
            uint32_t* bs = &Bs[bkr * BPAD + bcl];
            bs[0] = f2tf(pb0.x); bs[1] = f2tf(pb0.y);
            bs[2] = f2tf(pb0.z); bs[3] = f2tf(pb0.w);
            bs[4] = f2tf(pb1.x); bs[5] = f2tf(pb1.y);
            bs[6] = f2tf(pb1.z); bs[7] = f2tf(pb1.w);
        }
        __syncthreads();

        if (kt + 16 < K) {
            pa0 = *(const float4*)(Aptr + kt + 16);
            pa1 = *(const float4*)(Aptr + kt + 20);
            const float* bp = Bptr + (size_t)(kt + 16) * N;
            pb0 = *(const float4*)(bp);
            pb1 = *(const float4*)(bp + 4);
        }

        #pragma unroll
        for (int s = 0; s < 2; s++) {
            const int kk = s * 8;
            uint32_t af[4][4];
            uint32_t bf[4][2];
            #pragma unroll
            for (int mt = 0; mt < 4; mt++) {
                const int r0 = wm + mt * 16 + g;
                af[mt][0] = As[r0 * APAD + kk + c];
                af[mt][1] = As[(r0 + 8) * APAD + kk + c];
                af[mt][2] = As[r0 * APAD + kk + c + 4];
                af[mt][3] = As[(r0 + 8) * APAD + kk + c + 4];
            }
            #pragma unroll
            for (int nt = 0; nt < 4; nt++) {
                const int cc = wn + nt * 8 + g;
                bf[nt][0] = Bs[(kk + c) * BPAD + cc];
                bf[nt][1] = Bs[(kk + c + 4) * BPAD + cc];
            }
            #pragma unroll
            for (int mt = 0; mt < 4; mt++)
                #pragma unroll
                for (int nt = 0; nt < 4; nt++)
                    MMA_TF32(acc[mt][nt], af[mt], bf[nt]);
        }
        __syncthreads();
    }

    #pragma unroll
    for (int mt = 0; mt < 4; mt++) {
        const int row = m0 + wm + mt * 16 + g;
        #pragma unroll
        for (int nt = 0; nt < 4; nt++) {
            const int col = n0 + wn + nt * 8 + c * 2;
            float v0 = acc[mt][nt][0] * oscale;
            float v1 = acc[mt][nt][1] * oscale;
            float v2 = acc[mt][nt][2] * oscale;
            float v3 = acc[mt][nt][3] * oscale;
            if (round_out) {
                v0 = __uint_as_float(f2tf(v0));
                v1 = __uint_as_float(f2tf(v1));
                v2 = __uint_as_float(f2tf(v2));
                v3 = __uint_as_float(f2tf(v3));
            }
            *(float2*)&Cg[(size_t)row * N + col] = make_float2(v0, v1);
            *(float2*)&Cg[(size_t)(row + 8) * N + col] = make_float2(v2, v3);
        }
    }
}

// ---------------------------------------------------------------------------
// Dummy no-op kernel: placed before attention so attention is the 6th
// launch and gets captured by ncu (-s 5 -c 1). ~2us cost.
// ---------------------------------------------------------------------------
__global__ void dummy_k() { g_dummy[threadIdx.x & 31] = 0.f; }

// ---------------------------------------------------------------------------
// Tensor-core causal flash attention v5.
// q pre-scaled by 0.125*log2(e) and tf32-rounded; k/v tf32-rounded.
// K/V double-buffered via cp.async; softmax p = exp2(min(s,80)).
// Post-S phase fused per 8-key chunk (mask->exp2->shfl->PV MMA) to cut
// peak live registers (~95) and interleave MUFU/SHFL with tensor MMAs.
// ---------------------------------------------------------------------------
#define QST 68
#define KST 68
#define VST 72
#define ATTN_SMEM ((128 * QST + 2 * 64 * KST + 2 * 64 * VST) * 4)  // 104 KB

__global__ __launch_bounds__(256, 2)
void attn_tc5(const float* __restrict__ q, const float* __restrict__ k,
              const float* __restrict__ v, float* __restrict__ y) {
    extern __shared__ uint32_t sm_u[];
    uint32_t* Qs  = sm_u;                   // 128 x QST
    uint32_t* Ks0 = Qs + 128 * QST;
    uint32_t* Ks1 = Ks0 + 64 * KST;
    uint32_t* Vs0 = Ks1 + 64 * KST;
    uint32_t* Vs1 = Vs0 + 64 * VST;

    const int tid  = threadIdx.x;
    const int warp = tid >> 5;
    const int lane = tid & 31;
    const int g = lane >> 2;
    const int c = lane & 3;

    const int bh = blockIdx.x;
    const int b = bh >> 4;
    const int h = bh & 15;
    const int qt = (int)gridDim.y - 1 - (int)blockIdx.y;

    const int wm = warp * 16;
    const int row0g = qt * 128 + wm + g;
    const int row1g = row0g + 8;

    const uint32_t smem_base = (uint32_t)__cvta_generic_to_shared(sm_u);
    const uint32_t ks_addr[2] = { smem_base + (uint32_t)(128 * QST) * 4,
                                  smem_base + (uint32_t)(128 * QST + 64 * KST) * 4 };
    const uint32_t vs_addr[2] = { smem_base + (uint32_t)(128 * QST + 2 * 64 * KST) * 4,
                                  smem_base + (uint32_t)(128 * QST + 2 * 64 * KST + 64 * VST) * 4 };

    const int r_  = tid >> 2;
    const int cc_ = (tid & 3) * 16;
    const float* kgbase = k + ((size_t)(b * T_ + r_)) * C_ + h * HS_ + cc_;
    const float* vgbase = v + ((size_t)(b * T_ + r_)) * C_ + h * HS_ + cc_;
    const size_t tstep = (size_t)64 * C_;
    const uint32_t kdst_off = (uint32_t)(r_ * KST + cc_) * 4;
    const uint32_t vdst_off = (uint32_t)(r_ * VST + cc_) * 4;

    // ---- stage Q tile (raw tf32 bits, pre-scaled incl log2e) ----
    {
        const int lrq = tid >> 1;
        const int lcq = (tid & 1) * 32;
        const uint4* src = (const uint4*)(q + ((size_t)(b * T_ + qt * 128 + lrq)) * C_ + h * HS_ + lcq);
        uint4* dst = (uint4*)(Qs + lrq * QST + lcq);
        #pragma unroll
        for (int i = 0; i < 8; i++) dst[i] = src[i];
    }

    const int ktmax  = 2 * qt + 1;
    const int ktwmax = (qt * 128 + wm + 15) >> 6;
    const int maskfrom = (qt * 128 + wm) >> 6;

    // preload tile 0 -> buffer 0
    {
        #pragma unroll
        for (int i = 0; i < 4; i++) {
            cp_async16(ks_addr[0] + kdst_off + i * 16, kgbase + i * 4);
            cp_async16(vs_addr[0] + vdst_off + i * 16, vgbase + i * 4);
        }
        CP_COMMIT();
    }

    float o[8][4];
    #pragma unroll
    for (int nt = 0; nt < 8; nt++)
        #pragma unroll
        for (int r = 0; r < 4; r++) o[nt][r] = 0.f;
    float l0 = 0.f, l1 = 0.f;

    const int s1 = (lane & ~3) | (c >> 1);
    const int s2 = s1 + 2;
    const bool odd = (c & 1);

    for (int kt = 0; kt <= ktmax; kt++) {
        CP_WAIT0();
        __syncthreads();

        if (kt < ktmax) {
            const int nb = (kt + 1) & 1;
            const float* ksrc = kgbase + (size_t)(kt + 1) * tstep;
            const float* vsrc = vgbase + (size_t)(kt + 1) * tstep;
            #pragma unroll
            for (int i = 0; i < 4; i++) {
                cp_async16(ks_addr[nb] + kdst_off + i * 16, ksrc + i * 4);
                cp_async16(vs_addr[nb] + vdst_off + i * 16, vsrc + i * 4);
            }
            CP_COMMIT();
        }

        if (kt > ktwmax) continue;

        const uint32_t* Ks = (kt & 1) ? Ks1 : Ks0;
        const uint32_t* Vs = (kt & 1) ? Vs1 : Vs0;

        // ---- S = Q K^T ----
        float s[8][4];
        #pragma unroll
        for (int nt = 0; nt < 8; nt++)
            #pragma unroll
            for (int r = 0; r < 4; r++) s[nt][r] = 0.f;

        #pragma unroll
        for (int kk8 = 0; kk8 < 8; kk8++) {
            const int kk = kk8 * 8;
            uint32_t a[4];
            a[0] = Qs[(wm + g) * QST + kk + c];
            a[1] = Qs[(wm + g + 8) * QST + kk + c];
            a[2] = Qs[(wm + g) * QST + kk + c + 4];
            a[3] = Qs[(wm + g + 8) * QST + kk + c + 4];
            #pragma unroll
            for (int nt = 0; nt < 8; nt++) {
                uint32_t bf[2];
                bf[0] = Ks[(nt * 8 + g) * KST + kk + c];
                bf[1] = Ks[(nt * 8 + g) * KST + kk + c + 4];
                MMA_TF32(s[nt], a, bf);
            }
        }

        const bool domask = (kt >= maskfrom);

        // ---- fused per-chunk: mask -> exp2 -> shfl -> PV MMA ----
        #pragma unroll
        for (int j = 0; j < 8; j++) {
            if (domask) {
                const int col = kt * 64 + j * 8 + 2 * c;
                if (col     > row0g) s[j][0] = -1e30f;
                if (col + 1 > row0g) s[j][1] = -1e30f;
                if (col     > row1g) s[j][2] = -1e30f;
                if (col + 1 > row1g) s[j][3] = -1e30f;
            }
            float p0 = exp2f(fminf(s[j][0], 80.f));
            float p1 = exp2f(fminf(s[j][1], 80.f));
            float p2 = exp2f(fminf(s[j][2], 80.f));
            float p3 = exp2f(fminf(s[j][3], 80.f));
            l0 += p0 + p1;
            l1 += p2 + p3;

            float e0 = __shfl_sync(0xffffffffu, p0, s1);
            float e1 = __shfl_sync(0xffffffffu, p1, s1);
            float f0 = __shfl_sync(0xffffffffu, p0, s2);
            float f1 = __shfl_sync(0xffffffffu, p1, s2);
            float q0 = __shfl_sync(0xffffffffu, p2, s1);
            float q1 = __shfl_sync(0xffffffffu, p3, s1);
            float r0 = __shfl_sync(0xffffffffu, p2, s2);
            float r1 = __shfl_sync(0xffffffffu, p3, s2);

            uint32_t a[4];
            a[0] = f2tf(odd ? e1 : e0);   // P[g,    kk+c]
            a[1] = f2tf(odd ? q1 : q0);   // P[g+8,  kk+c]
            a[2] = f2tf(odd ? f1 : f0);   // P[g,    kk+c+4]
            a[3] = f2tf(odd ? r1 : r0);   // P[g+8,  kk+c+4]

            const int kk = j * 8;
            #pragma unroll
            for (int nt = 0; nt < 8; nt++) {
                uint32_t bf[2];
                bf[0] = Vs[(kk + c) * VST + nt * 8 + g];
                bf[1] = Vs[(kk + c + 4) * VST + nt * 8 + g];
                MMA_TF32(o[nt], a, bf);
            }
        }
    }

    // ---- reduce row sums across the 4 c-lanes (once) ----
    l0 += __shfl_xor_sync(0xffffffffu, l0, 1);
    l0 += __shfl_xor_sync(0xffffffffu, l0, 2);
    l1 += __shfl_xor_sync(0xffffffffu, l1, 1);
    l1 += __shfl_xor_sync(0xffffffffu, l1, 2);

    const float inv0 = 1.f / l0;
    const float inv1 = 1.f / l1;
    float* dst0 = y + ((size_t)(b * T_ + row0g)) * C_ + h * HS_;
    float* dst1 = y + ((size_t)(b * T_ + row1g)) * C_ + h * HS_;
    #pragma unroll
    for (int nt = 0; nt < 8; nt++) {
        const int col = nt * 8 + 2 * c;
        *(float2*)(dst0 + col) = make_float2(o[nt][0] * inv0, o[nt][1] * inv0);
        *(float2*)(dst1 + col) = make_float2(o[nt][2] * inv1, o[nt][3] * inv1);
    }
}

// ---------------------------------------------------------------------------
extern "C" void kernel_launch(void* const* d_in, const int* in_sizes, int n_in,
                              void* d_out, int out_size) {
    const float* x     = (const float*)d_in[0];
    const float* Wq    = (const float*)d_in[1];
    const float* Wkvd  = (const float*)d_in[2];
    const float* Wku   = (const float*)d_in[3];
    const float* Wvu   = (const float*)d_in[4];
    const float* Wout  = (const float*)d_in[5];
    float* out = (float*)d_out;

    float *q, *lat, *k, *v, *y;
    cudaGetSymbolAddress((void**)&q,   g_q);
    cudaGetSymbolAddress((void**)&lat, g_lat);
    cudaGetSymbolAddress((void**)&k,   g_k);
    cudaGetSymbolAddress((void**)&v,   g_v);
    cudaGetSymbolAddress((void**)&y,   g_y);

    cudaFuncSetAttribute(attn_tc5, cudaFuncAttributeMaxDynamicSharedMemorySize, ATTN_SMEM);

    dim3 blk(256);

    // q = (0.125*log2e) * (x @ Wq), tf32-rounded  (softmax uses exp2)
    gemm_tf32<<<dim3(C_ / 128, BT_ / 128), blk>>>(x, Wq, q, BT_, C_, C_, 0.18033688f, 1);
    gemm_tf32<<<dim3(L_ / 128, BT_ / 128), blk>>>(x, Wkvd, lat, BT_, L_, C_, 1.f, 0);
    gemm_tf32<<<dim3(C_ / 128, BT_ / 128), blk>>>(lat, Wku, k, BT_, C_, L_, 1.f, 1);
    gemm_tf32<<<dim3(C_ / 128, BT_ / 128), blk>>>(lat, Wvu, v, BT_, C_, L_, 1.f, 1);

    // launch #5: dummy, so attention below is launch #6 (ncu -s 5 -c 1)
    dummy_k<<<1, 32>>>();

    attn_tc5<<<dim3(B_ * H_, T_ / 128), 256, ATTN_SMEM>>>(q, k, v, y);

    gemm_tf32<<<dim3(C_ / 128, BT_ / 128), blk>>>(y, Wout, out, BT_, C_, C_, 1.f, 0);
}